// round 13
// baseline (speedup 1.0000x reference)
#include <cuda_runtime.h>
#include <cstdint>
#include <math.h>

#define Bq 128
#define Tq 512
#define Cq 100
#define Eq 64
#define Hq 256
#define KIN 320   // E+H

typedef unsigned long long ull;

// ---- scratch (device globals; no allocation in kernel_launch) ----
static __device__ float g_r[(size_t)Bq * Tq * Eq];          // rec_input
static __device__ int g_sink;                               // dummy-kernel sink

// SMEM float offsets
#define WS_OFF   0        // 35840: weights ((g*80+kq)*16 + jw)*4 + e  (h k<64, r k>=64)
#define BS_OFF   35840    // 112 bias + pad
#define HOWN_OFF 35952    // 512: own h slices [parity][stream][b2][j2]
#define HS_OFF   36464    // 2*2560: staged full-K operand, float4 idx b*80+kq
#define RED_OFF  41584    // 2*4480: partials (s*7+g)*160 + b*20 + j
#define MB_OFF   50544    // 4 mbarriers (u64): [stream][parity]
#define SMEM_FLT 50560    // 202,240 bytes

__device__ __forceinline__ float sigmf_(float x) { return 1.f / (1.f + expf(-x)); }
__device__ __forceinline__ float softplusf_(float x) {
    return fmaxf(x, 0.f) + log1pf(expf(-fabsf(x)));
}
__device__ __forceinline__ float sigf(float x) {
    return __fdividef(1.f, 1.f + __expf(-x));
}
__device__ __forceinline__ float tanf_(float x) {
    return 1.f - 2.f * __fdividef(1.f, 1.f + __expf(2.f * x));
}
__device__ __forceinline__ float splusf(float x) {
    return fmaxf(x, 0.f) + __logf(1.f + __expf(-fabsf(x)));
}
__device__ __forceinline__ void fma2_(ull& d, ull a, ull b) {
    asm volatile("fma.rn.f32x2 %0, %1, %2, %0;" : "+l"(d) : "l"(a), "l"(b));
}
__device__ __forceinline__ float lo_(ull v) { return __uint_as_float((unsigned)v); }
__device__ __forceinline__ float hi_(ull v) { return __uint_as_float((unsigned)(v >> 32)); }

__global__ void k_dummy() { if (threadIdx.x == 1024) g_sink = 1; }

// ---------------------------------------------------------------------------
// K1: rec_input[b,t,e] = (marks[b,t,:] @ W_emb[:,e]) / max(sum(marks),1)
// ---------------------------------------------------------------------------
__global__ __launch_bounds__(128) void k_embed(const float* __restrict__ marks,
                                               const float* __restrict__ Wemb) {
    int bt = blockIdx.x;
    __shared__ float sm[Cq];
    int tid = threadIdx.x;
    if (tid < Cq) sm[tid] = marks[(size_t)bt * Cq + tid];
    __syncthreads();
    if (tid < Eq) {
        float cnt = 0.f, s = 0.f;
        #pragma unroll
        for (int c = 0; c < Cq; c++) {
            float m = sm[c];
            cnt += m;
            s = fmaf(m, Wemb[c * Eq + tid], s);
        }
        g_r[(size_t)bt * Eq + tid] = s / fmaxf(cnt, 1.f);
    }
}

// ---------------------------------------------------------------------------
// K3: initial state -> out[b,0,:]
// ---------------------------------------------------------------------------
__global__ __launch_bounds__(256) void k_init(const float* __restrict__ init,
                                              float* __restrict__ out) {
    int b = blockIdx.x, k = threadIdx.x;
    float s0 = init[k], s1 = init[Hq + k], s2 = init[2 * Hq + k];
    float s3 = init[3 * Hq + k], s4 = init[4 * Hq + k], s5 = init[5 * Hq + k];
    float hd0 = tanhf(s0), cd0 = tanhf(s1), cb0 = tanhf(s2), c0 = tanhf(s3);
    float d0 = softplusf_(s4), o0 = sigmf_(s5);
    size_t base = (size_t)b * (Tq + 1) * (6 * Hq);
    out[base + 0 * Hq + k] = hd0;
    out[base + 1 * Hq + k] = o0;
    out[base + 2 * Hq + k] = cb0;
    out[base + 3 * Hq + k] = c0;
    out[base + 4 * Hq + k] = d0;
    out[base + 5 * Hq + k] = cd0;
}

// ---------------------------------------------------------------------------
// K4: fused recurrence, dual warp-specialized streams, CLUSTER DSMEM exchange.
//   grid = 128 = 8 clusters(batch groups of 16 b) x 16 cluster-ranks(j-slices).
//   Warps 0-3 = stream A (b 0..7), warps 4-7 = stream B (b 8..15).
//   h exchange: producers STS own 16j x 8b slice -> elected thread fires 16
//   remote mbarrier.arrives; consumers try_wait (HW sleep) then PULL peers'
//   slices via ld.shared::cluster. No L2 in the sync chain.
//   GEMM: per stream stid = (wid&3)*32 + lane; tile 7g x 4b x 80k (f32x2),
//   K=320 merged (h k<256, r k>=256). Reduction + phase2 as R9.
// ---------------------------------------------------------------------------
__global__ void __cluster_dims__(16, 1, 1) __launch_bounds__(256, 1)
k_recur(const float* __restrict__ Wc, const float* __restrict__ ts,
        const float* __restrict__ init, const float* __restrict__ bc,
        float* __restrict__ out) {
    extern __shared__ float sh[];
    uint32_t smem32 = (uint32_t)__cvta_generic_to_shared(sh);

    int tid = threadIdx.x;
    int lane = tid & 31;
    int wid = tid >> 5;
    int stream = wid >> 2;           // 0: b 0..7, 1: b 8..15
    int s = wid & 3;                 // k-split 0..3 (80 k each)
    int bg = lane >> 4, j1 = lane & 15;
    int bbase = bg * 4;
    int stid = tid & 127;
    int j2 = stid & 15, b2 = stid >> 4;

    int group = blockIdx.x >> 4;
    uint32_t rank;
    asm("mov.u32 %0, %%cluster_ctarank;" : "=r"(rank));
    int j0 = (int)rank * 16, jg = j0 + j2;
    int gb0 = group * 16 + stream * 8;
    int gbb = gb0 + b2;
    int barid = stream + 1;

    float* Ws   = sh + WS_OFF;
    float* bs   = sh + BS_OFF;
    float* hsS  = sh + HS_OFF  + stream * 2560;
    float* redS = sh + RED_OFF + stream * 4480;
    uint32_t mb_byte = smem32 + MB_OFF * 4;           // + (S*2+p)*8
    uint32_t hown_byte = smem32 + HOWN_OFF * 4;       // + ((p*2+S)*128 + b*16 + j)*4

    // one-time combined weight load: kq<64 -> h weights, kq>=64 -> r weights
    for (int idx = tid; idx < 35840; idx += 256) {
        int e = idx & 3, jw = (idx >> 2) & 15;
        int kq = (idx >> 6) % 80, g = (idx >> 6) / 80;
        int col = (kq < 64) ? (Eq + kq * 4 + e) : ((kq - 64) * 4 + e);
        Ws[idx] = Wc[(size_t)(g * Hq + j0 + jw) * KIN + col];
    }
    if (tid < 112) bs[tid] = bc[(tid >> 4) * Hq + j0 + (tid & 15)];

    // mbarrier init: 4 barriers [stream][parity], count 16 (one per producer CTA)
    if (tid == 0) {
        #pragma unroll
        for (int m = 0; m < 4; m++)
            asm volatile("mbarrier.init.shared.b64 [%0], %1;"
                         :: "r"(mb_byte + m * 8), "r"(16u) : "memory");
    }
    float c_st  = tanhf(init[3 * Hq + jg]);
    float cb_st = tanhf(init[2 * Hq + jg]);
    __syncthreads();
    asm volatile("barrier.cluster.arrive.aligned;" ::: "memory");
    asm volatile("barrier.cluster.wait.aligned;" ::: "memory");

    const ulonglong2* WU = (const ulonglong2*)Ws;
    const ulonglong2* HU = (const ulonglong2*)hsS;
    float4* hs4 = (float4*)hsS;
    const float4* gr4 = (const float4*)g_r;

    // gather identity
    int bb = stid >> 6, kqq = stid & 63;     // bb 0..1
    int peer = kqq >> 2, jq = kqq & 3;

    // h(0) from init (identical across b), r(0)/ts(0) prefetch
    float4 h0v;
    h0v.x = tanhf(init[kqq * 4 + 0]);
    h0v.y = tanhf(init[kqq * 4 + 1]);
    h0v.z = tanhf(init[kqq * 4 + 2]);
    h0v.w = tanhf(init[kqq * 4 + 3]);
    float4 pr = gr4[((size_t)gbb * Tq + 0) * 16 + j2];
    float ptc = ts[gbb * Tq + 0], ptp = 0.f;

    int ph0 = 0, ph1 = 0;   // mbarrier phase trackers [parity 0/1]

    #pragma unroll 1
    for (int t = 0; t < Tq; t++) {
        // ---- acquire + stage h ----
        if (t == 0) {
            #pragma unroll
            for (int i = 0; i < 4; i++)
                hs4[(bb + 2 * i) * 80 + kqq] = h0v;
        } else {
            int pb = t & 1;
            uint32_t mba = mb_byte + (stream * 2 + pb) * 8;
            int phase = pb ? ph1 : ph0;
            asm volatile(
                "{\n\t"
                ".reg .pred P;\n\t"
                "W%=:\n\t"
                "mbarrier.try_wait.parity.acquire.cluster.shared::cta.b64 P, [%0], %1, 0x989680;\n\t"
                "@P bra D%=;\n\t"
                "bra W%=;\n\t"
                "D%=:\n\t"
                "}"
                :: "r"(mba), "r"(phase) : "memory");
            if (pb) ph1 ^= 1; else ph0 ^= 1;

            // pull peers' slices (same peer for all 4 chunks of this thread)
            uint32_t la = hown_byte + ((uint32_t)(pb * 2 + stream) * 128 + jq * 4) * 4;
            uint32_t ra;
            asm volatile("mapa.shared::cluster.u32 %0, %1, %2;"
                         : "=r"(ra) : "r"(la), "r"(peer));
            #pragma unroll
            for (int i = 0; i < 4; i++) {
                ull v0, v1;
                uint32_t src = ra + (uint32_t)(bb + 2 * i) * 64;
                asm volatile("ld.shared::cluster.u64 %0, [%1];" : "=l"(v0) : "r"(src));
                asm volatile("ld.shared::cluster.u64 %0, [%1];" : "=l"(v1) : "r"(src + 8));
                uint32_t dst = smem32 + (uint32_t)(HS_OFF + stream * 2560
                               + ((bb + 2 * i) * 80 + kqq) * 4) * 4;
                asm volatile("st.shared.v2.u64 [%0], {%1, %2};"
                             :: "r"(dst), "l"(v0), "l"(v1) : "memory");
            }
        }
        // r part of the staged operand (kq 64..79)
        hs4[(stid >> 4) * 80 + 64 + (stid & 15)] = pr;
        float tc = ptc, tp = ptp;
        asm volatile("bar.sync %0, 128;" :: "r"(barid) : "memory");

        // ---- GEMM: 7 g x 4 b, k-split s (20 quads), packed f32x2 ----
        ull acc[7][4];
        #pragma unroll
        for (int g = 0; g < 7; g++)
            #pragma unroll
            for (int bi = 0; bi < 4; bi++) acc[g][bi] = 0ull;

        #pragma unroll
        for (int q = 0; q < 20; q++) {
            int kq = s * 20 + q;
            ulonglong2 hv[4];
            #pragma unroll
            for (int bi = 0; bi < 4; bi++)
                hv[bi] = HU[(bbase + bi) * 80 + kq];
            #pragma unroll
            for (int g = 0; g < 7; g++) {
                ulonglong2 wv = WU[(g * 80 + kq) * 16 + j1];
                #pragma unroll
                for (int bi = 0; bi < 4; bi++) {
                    fma2_(acc[g][bi], wv.x, hv[bi].x);
                    fma2_(acc[g][bi], wv.y, hv[bi].y);
                }
            }
        }

        // ---- store k-partials ----
        #pragma unroll
        for (int g = 0; g < 7; g++)
            #pragma unroll
            for (int bi = 0; bi < 4; bi++)
                redS[(s * 7 + g) * 160 + (bbase + bi) * 20 + j1] =
                    lo_(acc[g][bi]) + hi_(acc[g][bi]);
        asm volatile("bar.sync %0, 128;" :: "r"(barid) : "memory");

        // ---- phase 2: reduce 4 partials + gates + decay ----
        float gate[7];
        #pragma unroll
        for (int g = 0; g < 7; g++) {
            float vv = bs[g * 16 + j2];
            #pragma unroll
            for (int sp = 0; sp < 4; sp++)
                vv += redS[(sp * 7 + g) * 160 + b2 * 20 + j2];
            gate[g] = vv;
        }
        float gi  = sigf(gate[0]);
        float gf  = sigf(gate[1]);
        float gz  = tanf_(gate[2]);
        float go  = sigf(gate[3]);
        float gib = sigf(gate[4]);
        float gfb = sigf(gate[5]);
        float gd  = splusf(gate[6]);
        float dt  = tc - tp;

        float ct  = gf * c_st + gi * gz;
        float cbt = gfb * cb_st + gib * gz;
        float cdt = cbt + (ct - cbt) * __expf(-gd * dt);
        float hdt = go * tanf_(cdt);

        c_st = ct; cb_st = cbt;

        // write own h slice for t+1 (parity (t+1)&1)
        int p1 = (t + 1) & 1;
        sh[HOWN_OFF + (p1 * 2 + stream) * 128 + b2 * 16 + j2] = hdt;

        // ---- stream barrier orders the 128 STS, then broadcast arrives ----
        asm volatile("bar.sync %0, 128;" :: "r"(barid) : "memory");
        if (stid == 0 && t < Tq - 1) {
            uint32_t mbl = mb_byte + (uint32_t)(stream * 2 + p1) * 8;
            #pragma unroll
            for (int r = 0; r < 16; r++) {
                uint32_t ra;
                asm volatile("mapa.shared::cluster.u32 %0, %1, %2;"
                             : "=r"(ra) : "r"(mbl), "r"(r));
                asm volatile("mbarrier.arrive.shared::cluster.b64 _, [%0];"
                             :: "r"(ra) : "memory");
            }
        }

        // ---- prefetch next r / ts ----
        if (t < Tq - 1) {
            pr  = gr4[((size_t)gbb * Tq + t + 1) * 16 + j2];
            ptp = tc;
            ptc = ts[gbb * Tq + t + 1];
        }

        // ---- output writes (pure sinks) ----
        size_t ob = ((size_t)gbb * (Tq + 1) + t + 1) * (size_t)(6 * Hq) + jg;
        __stcs(&out[ob + 0 * Hq], hdt);
        __stcs(&out[ob + 1 * Hq], go);
        __stcs(&out[ob + 2 * Hq], cbt);
        __stcs(&out[ob + 3 * Hq], ct);
        __stcs(&out[ob + 4 * Hq], gd);
        __stcs(&out[ob + 5 * Hq], cdt);
    }

    // no CTA may exit while peers might still arrive on its mbarriers
    asm volatile("barrier.cluster.arrive.aligned;" ::: "memory");
    asm volatile("barrier.cluster.wait.aligned;" ::: "memory");
}

// ---------------------------------------------------------------------------
extern "C" void kernel_launch(void* const* d_in, const int* in_sizes, int n_in,
                              void* d_out, int out_size) {
    const float* marks = (const float*)d_in[0];
    const float* ts    = (const float*)d_in[1];
    const float* Wemb  = (const float*)d_in[2];
    const float* Wc    = (const float*)d_in[3];
    const float* bc    = (const float*)d_in[4];
    const float* init  = (const float*)d_in[5];
    float* out = (float*)d_out;

    k_dummy<<<1, 32>>>();                       // aligns ncu -s 5 onto k_recur
    k_embed<<<Bq * Tq, 128>>>(marks, Wemb);
    k_init<<<Bq, 256>>>(init, out);

    const int SMEM = SMEM_FLT * (int)sizeof(float);   // 202,240 B
    cudaFuncSetAttribute(k_recur, cudaFuncAttributeMaxDynamicSharedMemorySize, SMEM);
    cudaFuncSetAttribute(k_recur, cudaFuncAttributeNonPortableClusterSizeAllowed, 1);
    k_recur<<<128, 256, SMEM>>>(Wc, ts, init, bc, out);
}

// round 14
// speedup vs baseline: 2.0849x; 2.0849x over previous
#include <cuda_runtime.h>
#include <cstdint>
#include <math.h>

#define Bq 128
#define Tq 512
#define Cq 100
#define Eq 64
#define Hq 256
#define KIN 320   // E+H

typedef unsigned long long ull;

// ---- scratch (device globals; no allocation in kernel_launch) ----
static __device__ float g_r[(size_t)Bq * Tq * Eq];          // rec_input
static __device__ __align__(16) float g_h[2][Bq][Hq];       // ping-pong h_d [buf][b][j]
static __device__ unsigned g_cnt[32];                       // [stream*8 + group]
static __device__ int g_sink;                               // dummy-kernel sink

__device__ __forceinline__ float sigmf_(float x) { return 1.f / (1.f + expf(-x)); }
__device__ __forceinline__ float softplusf_(float x) {
    return fmaxf(x, 0.f) + log1pf(expf(-fabsf(x)));
}
// fast variants (abs err ~1e-6, budget 1e-3)
__device__ __forceinline__ float sigf(float x) {
    return __fdividef(1.f, 1.f + __expf(-x));
}
__device__ __forceinline__ float tanf_(float x) {
    return 1.f - 2.f * __fdividef(1.f, 1.f + __expf(2.f * x));
}
__device__ __forceinline__ float splusf(float x) {
    return fmaxf(x, 0.f) + __logf(1.f + __expf(-fabsf(x)));
}
__device__ __forceinline__ void fma2_(ull& d, ull a, ull b) {
    asm volatile("fma.rn.f32x2 %0, %1, %2, %0;" : "+l"(d) : "l"(a), "l"(b));
}
__device__ __forceinline__ float lo_(ull v) { return __uint_as_float((unsigned)v); }
__device__ __forceinline__ float hi_(ull v) { return __uint_as_float((unsigned)(v >> 32)); }

__global__ void k_dummy() { if (threadIdx.x == 1024) g_sink = 1; }

// ---------------------------------------------------------------------------
// K1: rec_input[b,t,e] = (marks[b,t,:] @ W_emb[:,e]) / max(sum(marks),1)
// ---------------------------------------------------------------------------
__global__ __launch_bounds__(128) void k_embed(const float* __restrict__ marks,
                                               const float* __restrict__ Wemb) {
    int bt = blockIdx.x;
    __shared__ float sm[Cq];
    int tid = threadIdx.x;
    if (tid < Cq) sm[tid] = marks[(size_t)bt * Cq + tid];
    __syncthreads();
    if (tid < Eq) {
        float cnt = 0.f, s = 0.f;
        #pragma unroll
        for (int c = 0; c < Cq; c++) {
            float m = sm[c];
            cnt += m;
            s = fmaf(m, Wemb[c * Eq + tid], s);
        }
        g_r[(size_t)bt * Eq + tid] = s / fmaxf(cnt, 1.f);
    }
}

// ---------------------------------------------------------------------------
// K3: initial state -> out[b,0,:], g_h[0], reset sync counters
// ---------------------------------------------------------------------------
__global__ __launch_bounds__(256) void k_init(const float* __restrict__ init,
                                              float* __restrict__ out) {
    int b = blockIdx.x, k = threadIdx.x;
    if (b == 0 && k < 32) g_cnt[k] = 0;
    float s0 = init[k], s1 = init[Hq + k], s2 = init[2 * Hq + k];
    float s3 = init[3 * Hq + k], s4 = init[4 * Hq + k], s5 = init[5 * Hq + k];
    float hd0 = tanhf(s0), cd0 = tanhf(s1), cb0 = tanhf(s2), c0 = tanhf(s3);
    float d0 = softplusf_(s4), o0 = sigmf_(s5);
    size_t base = (size_t)b * (Tq + 1) * (6 * Hq);
    out[base + 0 * Hq + k] = hd0;
    out[base + 1 * Hq + k] = o0;
    out[base + 2 * Hq + k] = cb0;
    out[base + 3 * Hq + k] = c0;
    out[base + 4 * Hq + k] = d0;
    out[base + 5 * Hq + k] = cd0;
    g_h[0][b][k] = hd0;
}

// ---------------------------------------------------------------------------
// K4: fused recurrence, FOUR warp-specialized streams (4 batches each).
//   grid = 128 = 8 batch-groups (16 b) x 16 j-slices (16 j). 256 threads.
//   Stream S = warps {2S, 2S+1}, 64 threads, batches gb0 = group*16 + S*4.
//   Each SMSP hosts warps of 2 different streams; 4 staggered sync chains
//   (~2.5-3k cyc each) hide under the other streams' GEMM issue.
//   Per stream: stid = s*16 + j1 (s: k-split of 80 over K=320 merged h|r);
//   thread tile 7 g x 4 b, fma.rn.f32x2. Named barrier (S+1, 64).
//   Sync: R9-proven per-(stream,group) counter, red.release + acquire poll.
// ---------------------------------------------------------------------------
__global__ void __launch_bounds__(256, 1)
k_recur(const float* __restrict__ Wc, const float* __restrict__ ts,
        const float* __restrict__ init, const float* __restrict__ bc,
        float* __restrict__ out) {
    extern __shared__ float sh[];
    float* Ws = sh;             // 35840: ((g*80+kq)*16 + jw)*4 + e  (h kq<64 | r)
    float* bs = sh + 35840;     //   112: bias g*16+j  (pad to 35952)
    float* hs = sh + 35952;     // 4*1280: staged K=320 operand, float4 b*80+kq
    float* red = sh + 41072;    // 4*2240: partials (s*7+g)*80 + b*20 + j

    int tid = threadIdx.x;
    int wid = tid >> 5;
    int stream = wid >> 1;           // 0..3, batches S*4..S*4+3
    int stid = (wid & 1) * 32 + (tid & 31);   // 0..63 within stream
    int s  = stid >> 4;              // k-split 0..3 (20 quads each)
    int j1 = stid & 15;
    int j2 = stid & 15, b2 = stid >> 4;       // phase-2: b2 0..3

    int group = blockIdx.x >> 4;     // 0..7
    int rank  = blockIdx.x & 15;     // 0..15
    int j0 = rank * 16, jg = j0 + j2;
    int gb0 = group * 16 + stream * 4;
    int gbb = gb0 + b2;              // this thread's output batch
    unsigned* cnt = g_cnt + stream * 8 + group;
    int barid = stream + 1;

    float* hsS  = hs  + stream * 1280;
    float* redS = red + stream * 2240;

    // one-time merged weight load (h cols for kq<64, r cols for kq>=64)
    for (int idx = tid; idx < 35840; idx += 256) {
        int e = idx & 3, jw = (idx >> 2) & 15;
        int kq = (idx >> 6) % 80, g = (idx >> 6) / 80;
        int col = (kq < 64) ? (Eq + kq * 4 + e) : ((kq - 64) * 4 + e);
        Ws[idx] = Wc[(size_t)(g * Hq + j0 + jw) * KIN + col];
    }
    if (tid < 112) bs[tid] = bc[(tid >> 4) * Hq + j0 + (tid & 15)];

    float c_st  = tanhf(init[3 * Hq + jg]);
    float cb_st = tanhf(init[2 * Hq + jg]);
    __syncthreads();   // last full-CTA barrier

    const ulonglong2* WU = (const ulonglong2*)Ws;
    const ulonglong2* HU = (const ulonglong2*)hsS;
    float4* hs4 = (float4*)hsS;
    const float4* gr4 = (const float4*)g_r;

    // prefetch regs + prologue (t = 0; h(0) published by k_init)
    float4 ph[4], pr;
    float ptc, ptp = 0.f;
    {
        const float4* gsrc = (const float4*)&g_h[0][0][0];
        #pragma unroll
        for (int i = 0; i < 4; i++)          // batch i of this stream
            ph[i] = __ldcg(gsrc + (gb0 + i) * 64 + stid);
        pr  = gr4[((size_t)gbb * Tq + 0) * 16 + j2];
        ptc = ts[gbb * Tq + 0];
    }

    for (int t = 0; t < Tq; t++) {
        // ---- stage from prefetch regs (h quads 0..63, r quads 64..79) ----
        #pragma unroll
        for (int i = 0; i < 4; i++)
            hs4[i * 80 + stid] = ph[i];
        hs4[b2 * 80 + 64 + j2] = pr;
        float tc = ptc, tp = ptp;
        asm volatile("bar.sync %0, 64;" :: "r"(barid) : "memory");

        // ---- GEMM: 7 g x 4 b, k-split s (20 quads of merged K=320) ----
        ull acc[7][4];
        #pragma unroll
        for (int g = 0; g < 7; g++)
            #pragma unroll
            for (int bi = 0; bi < 4; bi++) acc[g][bi] = 0ull;

        #pragma unroll
        for (int q = 0; q < 20; q++) {
            int kq = s * 20 + q;
            ulonglong2 hv[4];
            #pragma unroll
            for (int bi = 0; bi < 4; bi++)
                hv[bi] = HU[bi * 80 + kq];
            #pragma unroll
            for (int g = 0; g < 7; g++) {
                ulonglong2 wv = WU[(g * 80 + kq) * 16 + j1];
                #pragma unroll
                for (int bi = 0; bi < 4; bi++) {
                    fma2_(acc[g][bi], wv.x, hv[bi].x);
                    fma2_(acc[g][bi], wv.y, hv[bi].y);
                }
            }
        }

        // ---- store k-partials ----
        #pragma unroll
        for (int g = 0; g < 7; g++)
            #pragma unroll
            for (int bi = 0; bi < 4; bi++)
                redS[(s * 7 + g) * 80 + bi * 20 + j1] =
                    lo_(acc[g][bi]) + hi_(acc[g][bi]);
        asm volatile("bar.sync %0, 64;" :: "r"(barid) : "memory");

        // ---- phase 2: reduce 4 partials + gates + decay (1 out/thread) ----
        float gate[7];
        #pragma unroll
        for (int g = 0; g < 7; g++) {
            float vv = bs[g * 16 + j2];
            #pragma unroll
            for (int sp = 0; sp < 4; sp++)
                vv += redS[(sp * 7 + g) * 80 + b2 * 20 + j2];
            gate[g] = vv;
        }
        float gi  = sigf(gate[0]);
        float gf  = sigf(gate[1]);
        float gz  = tanf_(gate[2]);
        float go  = sigf(gate[3]);
        float gib = sigf(gate[4]);
        float gfb = sigf(gate[5]);
        float gd  = splusf(gate[6]);
        float dt  = tc - tp;

        float ct  = gf * c_st + gi * gz;
        float cbt = gfb * cb_st + gib * gz;
        float cdt = cbt + (ct - cbt) * __expf(-gd * dt);
        float hdt = go * tanf_(cdt);

        c_st = ct; cb_st = cbt;
        __stcg(&g_h[(t & 1) ^ 1][gbb][jg], hdt);

        // ---- release: stream barrier orders the 64 stcg, then publish ----
        asm volatile("bar.sync %0, 64;" :: "r"(barid) : "memory");
        if (stid == 0)
            asm volatile("red.release.gpu.global.add.u32 [%0], %1;"
                         :: "l"(cnt), "r"(1u) : "memory");

        // ---- out writes AFTER release ----
        size_t ob = ((size_t)gbb * (Tq + 1) + t + 1) * (size_t)(6 * Hq) + jg;
        __stcs(&out[ob + 0 * Hq], hdt);
        __stcs(&out[ob + 1 * Hq], go);
        __stcs(&out[ob + 2 * Hq], cbt);
        __stcs(&out[ob + 3 * Hq], ct);
        __stcs(&out[ob + 4 * Hq], gd);
        __stcs(&out[ob + 5 * Hq], cdt);

        // ---- poll + prefetch next step's h/r ----
        if (t < Tq - 1) {
            unsigned target = 16u * (unsigned)(t + 1), v;
            do {
                asm volatile("ld.acquire.gpu.u32 %0, [%1];"
                             : "=r"(v) : "l"(cnt) : "memory");
            } while (v < target);

            const float4* gsrc = (const float4*)&g_h[(t + 1) & 1][0][0];
            #pragma unroll
            for (int i = 0; i < 4; i++)
                ph[i] = __ldcg(gsrc + (gb0 + i) * 64 + stid);
            pr  = gr4[((size_t)gbb * Tq + t + 1) * 16 + j2];
            ptp = tc;
            ptc = ts[gbb * Tq + t + 1];
        }
    }
}

// ---------------------------------------------------------------------------
extern "C" void kernel_launch(void* const* d_in, const int* in_sizes, int n_in,
                              void* d_out, int out_size) {
    const float* marks = (const float*)d_in[0];
    const float* ts    = (const float*)d_in[1];
    const float* Wemb  = (const float*)d_in[2];
    const float* Wc    = (const float*)d_in[3];
    const float* bc    = (const float*)d_in[4];
    const float* init  = (const float*)d_in[5];
    float* out = (float*)d_out;

    k_dummy<<<1, 32>>>();                       // aligns ncu -s 5 onto k_recur
    k_embed<<<Bq * Tq, 128>>>(marks, Wemb);
    k_init<<<Bq, 256>>>(init, out);

    const int SMEM = 50032 * (int)sizeof(float);   // 200,128 B
    cudaFuncSetAttribute(k_recur, cudaFuncAttributeMaxDynamicSharedMemorySize, SMEM);
    k_recur<<<128, 256, SMEM>>>(Wc, ts, init, bc, out);
}

// round 16
// speedup vs baseline: 2.9064x; 1.3941x over previous
#include <cuda_runtime.h>
#include <cuda_bf16.h>
#include <cstdint>
#include <math.h>

#define Bq 128
#define Tq 512
#define Cq 100
#define Eq 64
#define Hq 256
#define KIN 320   // E+H

typedef unsigned long long ull;

// ---- scratch (device globals; no allocation in kernel_launch) ----
static __device__ float g_r[(size_t)Bq * Tq * Eq];          // rec_input
static __device__ __align__(16) float g_h[2][Bq][Hq];       // ping-pong h_d
static __device__ unsigned g_cnt[8];                        // per-group counters
static __device__ int g_sink;

// SMEM float offsets
#define ALO_F 0        // 17920: A_lo fragments [w][kk][lane] float4(4xb32)
#define BH_F  17920    //  2624: B_hi b32 [n][164]  (kp packing, pad 164)
#define BL_F  20544    //  2624: B_lo
#define RED_F 23168    //  2016: red [(g*16+j)*18 + b]
#define BS_F  25184    //   112: bias
#define SMEM_FLT 25344

__device__ __forceinline__ float sigmf_(float x) { return 1.f / (1.f + expf(-x)); }
__device__ __forceinline__ float softplusf_(float x) {
    return fmaxf(x, 0.f) + log1pf(expf(-fabsf(x)));
}
__device__ __forceinline__ float sigf(float x) {
    return __fdividef(1.f, 1.f + __expf(-x));
}
__device__ __forceinline__ float tanf_(float x) {
    return 1.f - 2.f * __fdividef(1.f, 1.f + __expf(2.f * x));
}
__device__ __forceinline__ float splusf(float x) {
    return fmaxf(x, 0.f) + __logf(1.f + __expf(-fabsf(x)));
}
__device__ __forceinline__ void bf16split_(float x, unsigned& h, unsigned& l) {
    __nv_bfloat16 bh = __float2bfloat16_rn(x);
    h = (unsigned)__bfloat16_as_ushort(bh);
    l = (unsigned)__bfloat16_as_ushort(__float2bfloat16_rn(x - __bfloat162float(bh)));
}
__device__ __forceinline__ void pack4_(float4 v, ull& hi, ull& lo) {
    unsigned h0, h1, h2, h3, l0, l1, l2, l3;
    bf16split_(v.x, h0, l0); bf16split_(v.y, h1, l1);
    bf16split_(v.z, h2, l2); bf16split_(v.w, h3, l3);
    hi = (ull)h0 | ((ull)h1 << 16) | ((ull)h2 << 32) | ((ull)h3 << 48);
    lo = (ull)l0 | ((ull)l1 << 16) | ((ull)l2 << 32) | ((ull)l3 << 48);
}

#define MMA_(d, a, b0, b1)                                                  \
    asm volatile("mma.sync.aligned.m16n8k16.row.col.f32.bf16.bf16.f32 "     \
                 "{%0,%1,%2,%3}, {%4,%5,%6,%7}, {%8,%9}, {%0,%1,%2,%3};"    \
                 : "+f"((d)[0]), "+f"((d)[1]), "+f"((d)[2]), "+f"((d)[3])   \
                 : "r"((a)[0]), "r"((a)[1]), "r"((a)[2]), "r"((a)[3]),      \
                   "r"(b0), "r"(b1))

__global__ void k_dummy() { if (threadIdx.x == 1024) g_sink = 1; }

// ---------------------------------------------------------------------------
// K1: rec_input
// ---------------------------------------------------------------------------
__global__ __launch_bounds__(128) void k_embed(const float* __restrict__ marks,
                                               const float* __restrict__ Wemb) {
    int bt = blockIdx.x;
    __shared__ float sm[Cq];
    int tid = threadIdx.x;
    if (tid < Cq) sm[tid] = marks[(size_t)bt * Cq + tid];
    __syncthreads();
    if (tid < Eq) {
        float cnt = 0.f, s = 0.f;
        #pragma unroll
        for (int c = 0; c < Cq; c++) {
            float m = sm[c];
            cnt += m;
            s = fmaf(m, Wemb[c * Eq + tid], s);
        }
        g_r[(size_t)bt * Eq + tid] = s / fmaxf(cnt, 1.f);
    }
}

// ---------------------------------------------------------------------------
// K3: initial state -> out[b,0,:], g_h[0], reset counters
// ---------------------------------------------------------------------------
__global__ __launch_bounds__(256) void k_init(const float* __restrict__ init,
                                              float* __restrict__ out) {
    int b = blockIdx.x, k = threadIdx.x;
    if (b == 0 && k < 8) g_cnt[k] = 0;
    float s0 = init[k], s1 = init[Hq + k], s2 = init[2 * Hq + k];
    float s3 = init[3 * Hq + k], s4 = init[4 * Hq + k], s5 = init[5 * Hq + k];
    float hd0 = tanhf(s0), cd0 = tanhf(s1), cb0 = tanhf(s2), c0 = tanhf(s3);
    float d0 = softplusf_(s4), o0 = sigmf_(s5);
    size_t base = (size_t)b * (Tq + 1) * (6 * Hq);
    out[base + 0 * Hq + k] = hd0;
    out[base + 1 * Hq + k] = o0;
    out[base + 2 * Hq + k] = cb0;
    out[base + 3 * Hq + k] = c0;
    out[base + 4 * Hq + k] = d0;
    out[base + 5 * Hq + k] = cd0;
    g_h[0][b][k] = hd0;
}

// ---------------------------------------------------------------------------
// K4: fused recurrence via mma.sync split-bf16 tensor cores.
//   grid = 128 = 8 batch-groups (16 b) x 16 j-slices. 256 threads.
//   Warp g (0..6) owns gate g: D-tile m16(j) x n16(b), K=320 (20 k-steps).
//   A = W: A_hi PERSISTENT IN REGISTERS (80 regs), A_lo in SMEM (LDS.128).
//   B = [h|r] staged per step from prefetch regs as split bf16 (hi/lo).
//   3 passes per k-step: Ahi*Bhi + Ahi*Blo + Alo*Bhi, fp32 accum.
//   Epilogue -> red SMEM -> R14 phase2 / stcg / counter release / poll.
// ---------------------------------------------------------------------------
__global__ void __launch_bounds__(256, 1)
k_recur(const float* __restrict__ Wc, const float* __restrict__ ts,
        const float* __restrict__ init, const float* __restrict__ bc,
        float* __restrict__ out) {
    extern __shared__ float sh[];
    uint32_t* BH = (uint32_t*)(sh + BH_F);
    uint32_t* BL = (uint32_t*)(sh + BL_F);
    float* red = sh + RED_F;
    float* bs  = sh + BS_F;

    int tid = threadIdx.x;
    int lane = tid & 31;
    int wid = tid >> 5;
    int gp = lane >> 2, tg = lane & 3;        // mma fragment identity
    int j2 = tid & 15, b2 = tid >> 4;         // phase-2 identity
    int group = blockIdx.x >> 4;
    int rank  = blockIdx.x & 15;
    int j0 = rank * 16, jg = j0 + j2;
    int gb0 = group * 16;
    int gbb = gb0 + b2;
    unsigned* cnt = g_cnt + group;

    // ---- one-time: A_hi fragments -> registers, A_lo fragments -> SMEM ----
    uint32_t ahi[20][4];
    if (wid < 7) {
        int g = wid;
        #pragma unroll
        for (int kk = 0; kk < 20; kk++) {
            #pragma unroll
            for (int fi = 0; fi < 4; fi++) {
                int r = gp + (fi & 1) * 8;                 // j row 0..15
                int c = kk * 16 + tg * 2 + (fi >> 1) * 8;  // k col
                int col0 = (c < 256) ? (Eq + c) : (c - 256);
                int col1 = (c + 1 < 256) ? (Eq + c + 1) : (c + 1 - 256);
                size_t rowoff = (size_t)(g * Hq + j0 + r) * KIN;
                float w0 = Wc[rowoff + col0];
                float w1 = Wc[rowoff + col1];
                unsigned h0, l0, h1, l1;
                bf16split_(w0, h0, l0);
                bf16split_(w1, h1, l1);
                ahi[kk][fi] = h0 | (h1 << 16);
                ((uint32_t*)sh)[ALO_F + ((wid * 20 + kk) * 32 + lane) * 4 + fi] =
                    l0 | (l1 << 16);
            }
        }
    }
    if (tid < 112) bs[tid] = bc[(tid >> 4) * Hq + j0 + (tid & 15)];

    float c_st  = tanhf(init[3 * Hq + jg]);
    float cb_st = tanhf(init[2 * Hq + jg]);
    __syncthreads();

    const float4* gr4 = (const float4*)g_r;

    // prefetch regs (t = 0; h(0) from k_init)
    float4 ph[4], pr;
    float ptc, ptp = 0.f;
    {
        const float4* gsrc = (const float4*)&g_h[0][0][0];
        #pragma unroll
        for (int i = 0; i < 4; i++) {
            int idx = tid + 256 * i;
            ph[i] = __ldcg(gsrc + (gb0 + (idx >> 6)) * 64 + (idx & 63));
        }
        pr  = gr4[((size_t)gbb * Tq + 0) * 16 + j2];
        ptc = ts[gbb * Tq + 0];
    }

    for (int t = 0; t < Tq; t++) {
        // ---- stage B = [h | r] as split-bf16, kp packing (conflict-free) ----
        #pragma unroll
        for (int i = 0; i < 4; i++) {
            int idx = tid + 256 * i;
            int b = idx >> 6, kq = idx & 63;
            ull vh, vl;
            pack4_(ph[i], vh, vl);
            *(ull*)&BH[b * 164 + 2 * kq] = vh;
            *(ull*)&BL[b * 164 + 2 * kq] = vl;
        }
        {
            ull vh, vl;
            pack4_(pr, vh, vl);
            *(ull*)&BH[b2 * 164 + 128 + 2 * j2] = vh;
            *(ull*)&BL[b2 * 164 + 128 + 2 * j2] = vl;
        }
        float tc = ptc, tp = ptp;
        __syncthreads();

        // ---- GEMM: warps 0..6, 3-pass split-bf16 mma ----
        if (wid < 7) {
            float d[2][4];
            #pragma unroll
            for (int nt = 0; nt < 2; nt++)
                #pragma unroll
                for (int i = 0; i < 4; i++) d[nt][i] = 0.f;

            #pragma unroll
            for (int kk = 0; kk < 20; kk++) {
                float4 al4 = *(const float4*)&sh[ALO_F
                               + ((wid * 20 + kk) * 32 + lane) * 4];
                uint32_t al[4] = {__float_as_uint(al4.x), __float_as_uint(al4.y),
                                  __float_as_uint(al4.z), __float_as_uint(al4.w)};
                #pragma unroll
                for (int nt = 0; nt < 2; nt++) {
                    int nb = nt * 8 + gp;
                    uint32_t bh0 = BH[nb * 164 + kk * 8 + tg];
                    uint32_t bh1 = BH[nb * 164 + kk * 8 + tg + 4];
                    uint32_t bl0 = BL[nb * 164 + kk * 8 + tg];
                    uint32_t bl1 = BL[nb * 164 + kk * 8 + tg + 4];
                    MMA_(d[nt], ahi[kk], bh0, bh1);
                    MMA_(d[nt], ahi[kk], bl0, bl1);
                    MMA_(d[nt], al, bh0, bh1);
                }
            }

            // epilogue: D frags -> red[(g*16+j)*18 + b]
            #pragma unroll
            for (int nt = 0; nt < 2; nt++) {
                int b = nt * 8 + tg * 2;
                *(float2*)&red[(wid * 16 + gp) * 18 + b] =
                    make_float2(d[nt][0], d[nt][1]);
                *(float2*)&red[(wid * 16 + gp + 8) * 18 + b] =
                    make_float2(d[nt][2], d[nt][3]);
            }
        }
        __syncthreads();

        // ---- phase 2: gates + decay + state update (1 out/thread) ----
        float gate[7];
        #pragma unroll
        for (int g = 0; g < 7; g++)
            gate[g] = red[(g * 16 + j2) * 18 + b2] + bs[g * 16 + j2];

        float gi  = sigf(gate[0]);
        float gf  = sigf(gate[1]);
        float gz  = tanf_(gate[2]);
        float go  = sigf(gate[3]);
        float gib = sigf(gate[4]);
        float gfb = sigf(gate[5]);
        float gd  = splusf(gate[6]);
        float dt  = tc - tp;

        float ct  = gf * c_st + gi * gz;
        float cbt = gfb * cb_st + gib * gz;
        float cdt = cbt + (ct - cbt) * __expf(-gd * dt);
        float hdt = go * tanf_(cdt);

        c_st = ct; cb_st = cbt;
        __stcg(&g_h[(t & 1) ^ 1][gbb][jg], hdt);

        // ---- release: bar orders all 256 stcg, tid0 publishes ----
        __syncthreads();
        if (tid == 0)
            asm volatile("red.release.gpu.global.add.u32 [%0], %1;"
                         :: "l"(cnt), "r"(1u) : "memory");

        // ---- out writes AFTER release ----
        size_t ob = ((size_t)gbb * (Tq + 1) + t + 1) * (size_t)(6 * Hq) + jg;
        __stcs(&out[ob + 0 * Hq], hdt);
        __stcs(&out[ob + 1 * Hq], go);
        __stcs(&out[ob + 2 * Hq], cbt);
        __stcs(&out[ob + 3 * Hq], ct);
        __stcs(&out[ob + 4 * Hq], gd);
        __stcs(&out[ob + 5 * Hq], cdt);

        // ---- poll + prefetch next h/r ----
        if (t < Tq - 1) {
            unsigned target = 16u * (unsigned)(t + 1), v;
            do {
                asm volatile("ld.acquire.gpu.u32 %0, [%1];"
                             : "=r"(v) : "l"(cnt) : "memory");
            } while (v < target);

            const float4* gsrc = (const float4*)&g_h[(t + 1) & 1][0][0];
            #pragma unroll
            for (int i = 0; i < 4; i++) {
                int idx = tid + 256 * i;
                ph[i] = __ldcg(gsrc + (gb0 + (idx >> 6)) * 64 + (idx & 63));
            }
            pr  = gr4[((size_t)gbb * Tq + t + 1) * 16 + j2];
            ptp = tc;
            ptc = ts[gbb * Tq + t + 1];
        }
    }
}

// ---------------------------------------------------------------------------
extern "C" void kernel_launch(void* const* d_in, const int* in_sizes, int n_in,
                              void* d_out, int out_size) {
    const float* marks = (const float*)d_in[0];
    const float* ts    = (const float*)d_in[1];
    const float* Wemb  = (const float*)d_in[2];
    const float* Wc    = (const float*)d_in[3];
    const float* bc    = (const float*)d_in[4];
    const float* init  = (const float*)d_in[5];
    float* out = (float*)d_out;

    k_dummy<<<1, 32>>>();                       // aligns ncu -s 5 onto k_recur
    k_embed<<<Bq * Tq, 128>>>(marks, Wemb);
    k_init<<<Bq, 256>>>(init, out);

    const int SMEM = SMEM_FLT * (int)sizeof(float);   // 101,376 B
    cudaFuncSetAttribute(k_recur, cudaFuncAttributeMaxDynamicSharedMemorySize, SMEM);
    k_recur<<<128, 256, SMEM>>>(Wc, ts, init, bc, out);
}